// round 14
// baseline (speedup 1.0000x reference)
#include <cuda_runtime.h>
#include <cstdint>

#define SEQ    2048
#define EMB    2048
#define NQKV   3072
#define NHEADS 16
#define CEXP   0.12751743200183823f            // (1/sqrt(128)) * log2(e)

// fp16 scratch (allocation-free rule: __device__ globals)
__device__ uint16_t g_xh  [SEQ * EMB];         // x fp16
__device__ uint16_t g_wh  [NQKV * EMB];        // concat(Wq, Wlk, Wlv) fp16
__device__ uint16_t g_woh [EMB * EMB];         // Wo fp16
__device__ uint16_t g_qlkv[SEQ * NQKV];        // q*CEXP | lk | lv  fp16
__device__ uint16_t g_vT  [NHEADS * 32 * SEQ]; // lv transposed: [h][d][t]
__device__ uint16_t g_aoh [SEQ * EMB];         // attention out fp16

// ---------------------------------------------------------------------------
// helpers
// ---------------------------------------------------------------------------
__device__ __forceinline__ uint32_t pack_f16(float lo, float hi) {
    uint32_t r;
    asm("cvt.rn.f16x2.f32 %0, %1, %2;" : "=r"(r) : "f"(hi), "f"(lo));
    return r;
}
__device__ __forceinline__ float ex2(float x) {
    float r;
    asm("ex2.approx.ftz.f32 %0, %1;" : "=f"(r) : "f"(x));
    return r;
}
#define CP_ASYNC16(dst, src) \
    asm volatile("cp.async.cg.shared.global [%0], [%1], 16;" :: "r"(dst), "l"(src))
#define CP_COMMIT() asm volatile("cp.async.commit_group;" ::: "memory")
#define CP_WAIT(n)  asm volatile("cp.async.wait_group %0;" :: "n"(n) : "memory")

__device__ __forceinline__ uint32_t smem_u32(const void* p) {
    uint32_t a;
    asm("{ .reg .u64 t; cvta.to.shared.u64 t, %1; cvt.u32.u64 %0, t; }"
        : "=r"(a) : "l"(p));
    return a;
}
__device__ __forceinline__ void mma_f16(float& c0, float& c1, float& c2, float& c3,
                                        uint32_t a0, uint32_t a1, uint32_t a2, uint32_t a3,
                                        uint32_t b0, uint32_t b1) {
    asm volatile(
        "mma.sync.aligned.m16n8k16.row.col.f32.f16.f16.f32 "
        "{%0,%1,%2,%3}, {%4,%5,%6,%7}, {%8,%9}, {%0,%1,%2,%3};"
        : "+f"(c0), "+f"(c1), "+f"(c2), "+f"(c3)
        : "r"(a0), "r"(a1), "r"(a2), "r"(a3), "r"(b0), "r"(b1));
}
__device__ __forceinline__ void ldsm4(uint32_t& r0, uint32_t& r1, uint32_t& r2,
                                      uint32_t& r3, uint32_t addr) {
    asm volatile("ldmatrix.sync.aligned.m8n8.x4.shared.b16 {%0,%1,%2,%3}, [%4];"
                 : "=r"(r0), "=r"(r1), "=r"(r2), "=r"(r3) : "r"(addr));
}

// ---------------------------------------------------------------------------
// fused fp32 -> fp16 convert for all 5 tensors (one launch)
// ---------------------------------------------------------------------------
#define W1 (SEQ * EMB / 2)
#define W2 (512 * EMB / 2)
#define WTOT (3 * W1 + 2 * W2)

__global__ __launch_bounds__(256) void cvt_all(
    const float* __restrict__ x,   const float* __restrict__ Wq,
    const float* __restrict__ Wlk, const float* __restrict__ Wlv,
    const float* __restrict__ Wo)
{
    int i = blockIdx.x * 256 + threadIdx.x;
    if (i >= WTOT) return;
    const float* src;
    uint16_t* dst;
    int off;
    if (i < W1)               { src = x;   dst = g_xh;               off = i; }
    else if (i < 2 * W1)      { src = Wq;  dst = g_wh;               off = i - W1; }
    else if (i < 2 * W1 + W2) { src = Wlk; dst = g_wh + 2048 * EMB;  off = i - 2 * W1; }
    else if (i < 2 * W1 + 2 * W2) { src = Wlv; dst = g_wh + 2560 * EMB; off = i - 2 * W1 - W2; }
    else                      { src = Wo;  dst = g_woh;              off = i - 2 * W1 - 2 * W2; }
    float2 v = ((const float2*)src)[off];
    ((uint32_t*)dst)[off] = pack_f16(v.x, v.y);
}

// ---------------------------------------------------------------------------
// fp16 GEMM: C[128x128] = A[128xK] @ B[128xK]^T  (NT, K-major, fp16 in)
// 256 threads = 8 warps (2 x 4), warp tile 64x32, BK=32,
// 3-stage cp.async pipeline, 2 CTAs/SM. OUT16 path scales by `escale`
// (folds the attention softmax constant into the q columns).
// ---------------------------------------------------------------------------
#define BK     32
#define NCH    (EMB / BK)           // 64
#define ROWW   20                   // words per smem row
#define TILEB  (128 * ROWW * 4)     // 10240 bytes (A or B, one stage)
#define STAGEB (2 * TILEB)          // 20480 bytes per stage (A+B)
#define NSTAGE 3
#define GEMM_SMEM (NSTAGE * STAGEB) // 61440 B

template<int OUT16>
__device__ __forceinline__ void gemm_core_h(
    const uint16_t* __restrict__ A, const uint16_t* __restrict__ B,
    void* __restrict__ Cv, int ldc, float escale, char* sm)
{
    const uint32_t sbase = smem_u32(sm);
    const int tid  = threadIdx.x;
    const int wid  = tid >> 5;
    const int lane = tid & 31;
    const int wr   = wid >> 2;
    const int wc   = wid & 3;
    const int g    = lane >> 2;
    const int tig  = lane & 3;
    const int lq   = lane & 7;
    const int lb3  = (lane >> 3) & 1;
    const int lb4  = lane >> 4;

    const uint32_t a_frag = sbase + (uint32_t)((wr * 64 + lq + lb3 * 8) * 80 + lb4 * 16);
    const uint32_t b_frag = sbase + TILEB
                          + (uint32_t)((wc * 32 + lq + lb4 * 8) * 80 + lb3 * 16);

    float acc[4][4][4];
#pragma unroll
    for (int mi = 0; mi < 4; ++mi)
#pragma unroll
        for (int ni = 0; ni < 4; ++ni)
#pragma unroll
            for (int r = 0; r < 4; ++r) acc[mi][ni][r] = 0.f;

    auto loadTiles = [&](int kc) {
        const uint32_t stg = (uint32_t)(kc % NSTAGE) * STAGEB;
        const uint32_t abuf = sbase + stg;
        const uint32_t bbuf = sbase + stg + TILEB;
#pragma unroll
        for (int i = 0; i < 2; ++i) {
            int cid = tid + i * 256;        // 512 chunks: row = cid>>2, c = cid&3
            int row = cid >> 2, c = cid & 3;
            CP_ASYNC16(abuf + row * 80 + c * 16, A + (size_t)row * EMB + kc * BK + c * 8);
            CP_ASYNC16(bbuf + row * 80 + c * 16, B + (size_t)row * EMB + kc * BK + c * 8);
        }
    };

    loadTiles(0); CP_COMMIT();
    loadTiles(1); CP_COMMIT();

    for (int kc = 0; kc < NCH; ++kc) {
        if (kc < NCH - 1) { CP_WAIT(1); }
        else              { CP_WAIT(0); }
        __syncthreads();
        // stage (kc+2)%3 was last read at compute(kc-1), finished before this
        // barrier -> safe to refill now, overlapping with compute(kc).
        if (kc + 2 < NCH) { loadTiles(kc + 2); CP_COMMIT(); }

        const uint32_t boff = (uint32_t)(kc % NSTAGE) * STAGEB;

#pragma unroll
        for (int s = 0; s < 2; ++s) {
            uint32_t af[4][4], bf[4][2];
#pragma unroll
            for (int mi = 0; mi < 4; ++mi)
                ldsm4(af[mi][0], af[mi][1], af[mi][2], af[mi][3],
                      a_frag + boff + s * 32 + mi * 1280);
            ldsm4(bf[0][0], bf[0][1], bf[1][0], bf[1][1], b_frag + boff + s * 32);
            ldsm4(bf[2][0], bf[2][1], bf[3][0], bf[3][1], b_frag + boff + s * 32 + 1280);
#pragma unroll
            for (int mi = 0; mi < 4; ++mi)
#pragma unroll
                for (int ni = 0; ni < 4; ++ni)
                    mma_f16(acc[mi][ni][0], acc[mi][ni][1], acc[mi][ni][2], acc[mi][ni][3],
                            af[mi][0], af[mi][1], af[mi][2], af[mi][3],
                            bf[ni][0], bf[ni][1]);
        }
    }

#pragma unroll
    for (int mi = 0; mi < 4; ++mi) {
        const int r = wr * 64 + mi * 16 + g;
#pragma unroll
        for (int ni = 0; ni < 4; ++ni) {
            const int c = wc * 32 + ni * 8 + tig * 2;
            if (OUT16) {
                uint16_t* C16 = (uint16_t*)Cv;
                *(uint32_t*)(C16 + (size_t)r * ldc + c) =
                    pack_f16(acc[mi][ni][0] * escale, acc[mi][ni][1] * escale);
                *(uint32_t*)(C16 + (size_t)(r + 8) * ldc + c) =
                    pack_f16(acc[mi][ni][2] * escale, acc[mi][ni][3] * escale);
            } else {
                float* C = (float*)Cv;
                *(float2*)(C + (size_t)r * ldc + c) =
                    make_float2(acc[mi][ni][0], acc[mi][ni][1]);
                *(float2*)(C + (size_t)(r + 8) * ldc + c) =
                    make_float2(acc[mi][ni][2], acc[mi][ni][3]);
            }
        }
    }
}

// GEMM1: g_qlkv = xh @ wh^T  (fp16 out; q columns pre-scaled by CEXP)
__global__ __launch_bounds__(256, 2) void gemm1_h()
{
    extern __shared__ __align__(16) char sm[];
    const int n0 = blockIdx.x * 128;
    const int m0 = blockIdx.y * 128;
    const float escale = (n0 < 2048) ? CEXP : 1.0f;
    gemm_core_h<1>(g_xh + (size_t)m0 * EMB, g_wh + (size_t)n0 * EMB,
                   g_qlkv + (size_t)m0 * NQKV + n0, NQKV, escale, sm);
}

// GEMM2: out = aoh @ woh^T  (fp32 out)
__global__ __launch_bounds__(256, 2) void gemm2_h(float* __restrict__ out)
{
    extern __shared__ __align__(16) char sm[];
    const int n0 = blockIdx.x * 128;
    const int m0 = blockIdx.y * 128;
    gemm_core_h<0>(g_aoh + (size_t)m0 * EMB, g_woh + (size_t)n0 * EMB,
                   out + (size_t)m0 * EMB + n0, EMB, 1.0f, sm);
}

// ---------------------------------------------------------------------------
// V transpose: g_qlkv lv section [t][2560 + h*32 + d] -> g_vT[h][d][t]
// ---------------------------------------------------------------------------
__global__ __launch_bounds__(256) void transpose_v()
{
    __shared__ uint16_t tile[32 * 136];
    const int h  = blockIdx.y;
    const int t0 = blockIdx.x * 128;
    const int tid = threadIdx.x;
#pragma unroll
    for (int i = 0; i < 8; ++i) {
        int w = tid + i * 256;              // 2048 words: t = w>>4, dp = w&15
        int t = w >> 4, dp = w & 15;
        uint32_t v = *(const uint32_t*)(g_qlkv + (size_t)(t0 + t) * NQKV + 2560 + h * 32 + dp * 2);
        tile[(2 * dp) * 136 + t]     = (uint16_t)(v & 0xFFFF);
        tile[(2 * dp + 1) * 136 + t] = (uint16_t)(v >> 16);
    }
    __syncthreads();
#pragma unroll
    for (int i = 0; i < 8; ++i) {
        int o = tid + i * 256;              // 2048 words: d = o>>6, tw = o&63
        int d = o >> 6, tw = o & 63;
        uint32_t v = *(const uint32_t*)(tile + d * 136 + tw * 2);
        *(uint32_t*)(g_vT + (size_t)(h * 32 + d) * SEQ + t0 + tw * 2) = v;
    }
}

// ---------------------------------------------------------------------------
// fp16 tensor-core flash attention (max-free softmax), P in registers,
// q pre-scaled by CEXP -> softmax is a bare ex2 on the accumulator.
// 3-stage KV cp.async pipeline, ONE barrier per s-tile.
// CTA: one (h, grp), 128 q-rows, 8 warps x 16 rows, 16 s-tiles of 128.
// 2 CTAs/SM (smem 67.1KB, regs capped 128).
// ---------------------------------------------------------------------------
#define KTW    (128 * ROWW)                 // 2560 words per K tile
#define VTW    (32 * 68)                    // 2176 words per V tile
#define KVW    (KTW + VTW)                  // 4736 words per buffer
#define NKVSTG 3
#define QS_OFFW (NKVSTG * KVW)              // Q staging after the KV stages
#define ATTN_SMEM ((QS_OFFW + 128 * ROWW) * 4)    // 67072 bytes

__global__ __launch_bounds__(256, 2) void attn_h()
{
    extern __shared__ __align__(16) char sm[];
    uint32_t* smw = (uint32_t*)sm;
    const uint32_t sbase = smem_u32(sm);
    const int hg  = blockIdx.y;
    const int h   = hg >> 2;
    const int grp = hg & 3;
    const int q0  = blockIdx.x * 128;
    const int tid = threadIdx.x;
    const int wid = tid >> 5;
    const int lane = tid & 31;
    const int g   = lane >> 2;
    const int tig = lane & 3;
    const int lq  = lane & 7;
    const int lb3 = (lane >> 3) & 1;
    const int lb4 = lane >> 4;
    const int qcol = h * 128 + grp * 32;

    // per-lane ldmatrix address components
    const uint32_t k_frag = (uint32_t)((lq + lb4 * 8) * 80 + lb3 * 16);
    const uint32_t v_frag = (uint32_t)(KTW * 4 + (lq + lb4 * 8) * 272 + lb3 * 16);

    // ---- stage Q tile (fp16, pre-scaled by CEXP), 20-word rows
    uint32_t* Qs = smw + QS_OFFW;
#pragma unroll
    for (int i = 0; i < 2; ++i) {
        int cid = tid + i * 256;            // 512 chunks: row = cid>>2, c = cid&3
        int row = cid >> 2, c = cid & 3;
        uint4 v = *(const uint4*)(g_qlkv + (size_t)(q0 + row) * NQKV + qcol + c * 8);
        *(uint4*)(Qs + row * ROWW + c * 4) = v;
    }
    __syncthreads();

    uint32_t qa[2][4];
    {
        const uint32_t q_frag = sbase + QS_OFFW * 4
                              + (uint32_t)((wid * 16 + lq + lb3 * 8) * 80 + lb4 * 16);
#pragma unroll
        for (int s = 0; s < 2; ++s)
            ldsm4(qa[s][0], qa[s][1], qa[s][2], qa[s][3], q_frag + s * 32);
    }

    float o[4][4];
#pragma unroll
    for (int nd = 0; nd < 4; ++nd)
#pragma unroll
        for (int r = 0; r < 4; ++r) o[nd][r] = 0.f;
    float lsum0 = 0.f, lsum1 = 0.f;

    auto prefetch = [&](int st) {
        const uint32_t stg = (uint32_t)(st % NKVSTG) * (KVW * 4);
        uint32_t kb = sbase + stg;
        uint32_t vb = kb + KTW * 4;
        const uint16_t* kp = g_qlkv + (size_t)(st * 128) * NQKV + 2048 + h * 32;
        const uint16_t* vp = g_vT + (size_t)(h * 32) * SEQ + st * 128;
#pragma unroll
        for (int i = 0; i < 2; ++i) {
            int cid = tid + i * 256;
            {   // K: 512 chunks, row = cid>>2 (0..127), c = cid&3
                int row = cid >> 2, c = cid & 3;
                CP_ASYNC16(kb + row * 80 + c * 16, kp + (size_t)row * NQKV + c * 8);
            }
            {   // V: 512 chunks, row d = cid>>4 (0..31), c = cid&15
                int d = cid >> 4, c = cid & 15;
                CP_ASYNC16(vb + d * 272 + c * 16, vp + (size_t)d * SEQ + c * 8);
            }
        }
    };

    prefetch(0); CP_COMMIT();
    prefetch(1); CP_COMMIT();

    for (int st = 0; st < 16; ++st) {
        if (st < 15) { CP_WAIT(1); }
        else         { CP_WAIT(0); }
        __syncthreads();
        // stage (st+2)%3 was last read at compute(st-1), finished before this
        // barrier -> refill now, overlapped with compute(st).
        if (st + 2 < 16) { prefetch(st + 2); CP_COMMIT(); }

        const uint32_t stg = (uint32_t)(st % NKVSTG) * (KVW * 4);
        const uint32_t kbase = sbase + stg + k_frag;
        const uint32_t vbase = sbase + stg + v_frag;

        // ---- S = Q @ K^T  (q pre-scaled: acc is already log2-domain score)
        float acc[16][4];
#pragma unroll
        for (int ni = 0; ni < 16; ++ni)
#pragma unroll
            for (int r = 0; r < 4; ++r) acc[ni][r] = 0.f;

#pragma unroll
        for (int p = 0; p < 8; ++p) {
#pragma unroll
            for (int s = 0; s < 2; ++s) {
                uint32_t f0, f1, f2, f3;   // (ni=2p,k0)(2p,k8)(2p+1,k0)(2p+1,k8)
                ldsm4(f0, f1, f2, f3, kbase + p * 1280 + s * 32);
                mma_f16(acc[2*p][0], acc[2*p][1], acc[2*p][2], acc[2*p][3],
                        qa[s][0], qa[s][1], qa[s][2], qa[s][3], f0, f1);
                mma_f16(acc[2*p+1][0], acc[2*p+1][1], acc[2*p+1][2], acc[2*p+1][3],
                        qa[s][0], qa[s][1], qa[s][2], qa[s][3], f2, f3);
            }
        }

        // ---- softmax + P@V fused per k16 chunk; P never leaves registers.
#pragma unroll
        for (int kc = 0; kc < 8; ++kc) {
            const int n0i = 2 * kc, n1i = 2 * kc + 1;
            float a0 = ex2(acc[n0i][0]), a1 = ex2(acc[n0i][1]);
            float a2 = ex2(acc[n0i][2]), a3 = ex2(acc[n0i][3]);
            float b0 = ex2(acc[n1i][0]), b1 = ex2(acc[n1i][1]);
            float b2 = ex2(acc[n1i][2]), b3 = ex2(acc[n1i][3]);
            lsum0 += (a0 + a1) + (b0 + b1);
            lsum1 += (a2 + a3) + (b2 + b3);
            uint32_t pa0 = pack_f16(a0, a1);   // row g,   k 2tig..+1  (tile n0i)
            uint32_t pa1 = pack_f16(a2, a3);   // row g+8, k 2tig..+1
            uint32_t pa2 = pack_f16(b0, b1);   // row g,   k 8+2tig..+1 (tile n1i)
            uint32_t pa3 = pack_f16(b2, b3);   // row g+8, k 8+2tig..+1
            uint32_t vf[4][2];
            ldsm4(vf[0][0], vf[0][1], vf[1][0], vf[1][1], vbase + kc * 32);
            ldsm4(vf[2][0], vf[2][1], vf[3][0], vf[3][1], vbase + 16 * 272 + kc * 32);
#pragma unroll
            for (int nd = 0; nd < 4; ++nd)
                mma_f16(o[nd][0], o[nd][1], o[nd][2], o[nd][3],
                        pa0, pa1, pa2, pa3, vf[nd][0], vf[nd][1]);
        }
    }

    // ---- finalize: quad-reduce row sums, normalize, store fp16
    lsum0 += __shfl_xor_sync(0xFFFFFFFFu, lsum0, 1);
    lsum0 += __shfl_xor_sync(0xFFFFFFFFu, lsum0, 2);
    lsum1 += __shfl_xor_sync(0xFFFFFFFFu, lsum1, 1);
    lsum1 += __shfl_xor_sync(0xFFFFFFFFu, lsum1, 2);
    const float inv0 = 1.f / lsum0;
    const float inv1 = 1.f / lsum1;

    const int qr = q0 + wid * 16 + g;
    uint16_t* op0 = g_aoh + (size_t)qr * EMB + qcol;
    uint16_t* op1 = g_aoh + (size_t)(qr + 8) * EMB + qcol;
#pragma unroll
    for (int nd = 0; nd < 4; ++nd) {
        *(uint32_t*)(op0 + 8 * nd + 2 * tig) = pack_f16(o[nd][0] * inv0, o[nd][1] * inv0);
        *(uint32_t*)(op1 + 8 * nd + 2 * tig) = pack_f16(o[nd][2] * inv1, o[nd][3] * inv1);
    }
}

// ---------------------------------------------------------------------------
extern "C" void kernel_launch(void* const* d_in, const int* in_sizes, int n_in,
                              void* d_out, int out_size)
{
    const float* x   = (const float*)d_in[0];
    const float* Wq  = (const float*)d_in[1];
    // d_in[2] (Wk) and d_in[3] (Wv) are dead in the reference forward — skipped.
    const float* Wlk = (const float*)d_in[4];
    const float* Wlv = (const float*)d_in[5];
    const float* Wo  = (const float*)d_in[6];
    float* out = (float*)d_out;

    cudaFuncSetAttribute(gemm1_h, cudaFuncAttributeMaxDynamicSharedMemorySize, GEMM_SMEM);
    cudaFuncSetAttribute(gemm2_h, cudaFuncAttributeMaxDynamicSharedMemorySize, GEMM_SMEM);
    cudaFuncSetAttribute(attn_h,  cudaFuncAttributeMaxDynamicSharedMemorySize, ATTN_SMEM);

    cvt_all<<<(WTOT + 255) / 256, 256>>>(x, Wq, Wlk, Wlv, Wo);
    gemm1_h<<<dim3(NQKV / 128, SEQ / 128), 256, GEMM_SMEM>>>();
    transpose_v<<<dim3(SEQ / 128, NHEADS), 256>>>();
    attn_h<<<dim3(SEQ / 128, NHEADS * 4), 256, ATTN_SMEM>>>();
    gemm2_h<<<dim3(EMB / 128, SEQ / 128), 256, GEMM_SMEM>>>(out);
}

// round 16
// speedup vs baseline: 1.0865x; 1.0865x over previous
#include <cuda_runtime.h>
#include <cstdint>

#define SEQ    2048
#define EMB    2048
#define NQKV   3072
#define NHEADS 16
#define CEXP   0.12751743200183823f            // (1/sqrt(128)) * log2(e)

// fp16 scratch (allocation-free rule: __device__ globals)
__device__ uint16_t g_xh  [SEQ * EMB];         // x fp16
__device__ uint16_t g_wh  [NQKV * EMB];        // concat(Wq, Wlk, Wlv) fp16
__device__ uint16_t g_woh [EMB * EMB];         // Wo fp16
__device__ uint16_t g_qlkv[SEQ * NQKV];        // q*CEXP | lk | lv  fp16
__device__ uint16_t g_vT  [NHEADS * 32 * SEQ]; // lv transposed: [h][d][t]
__device__ uint16_t g_aoh [SEQ * EMB];         // attention out fp16

// ---------------------------------------------------------------------------
// helpers
// ---------------------------------------------------------------------------
__device__ __forceinline__ uint32_t pack_f16(float lo, float hi) {
    uint32_t r;
    asm("cvt.rn.f16x2.f32 %0, %1, %2;" : "=r"(r) : "f"(hi), "f"(lo));
    return r;
}
__device__ __forceinline__ float ex2(float x) {
    float r;
    asm("ex2.approx.ftz.f32 %0, %1;" : "=f"(r) : "f"(x));
    return r;
}
#define CP_ASYNC16(dst, src) \
    asm volatile("cp.async.cg.shared.global [%0], [%1], 16;" :: "r"(dst), "l"(src))
#define CP_COMMIT() asm volatile("cp.async.commit_group;" ::: "memory")
#define CP_WAIT(n)  asm volatile("cp.async.wait_group %0;" :: "n"(n) : "memory")

__device__ __forceinline__ uint32_t smem_u32(const void* p) {
    uint32_t a;
    asm("{ .reg .u64 t; cvta.to.shared.u64 t, %1; cvt.u32.u64 %0, t; }"
        : "=r"(a) : "l"(p));
    return a;
}
__device__ __forceinline__ void mma_f16(float& c0, float& c1, float& c2, float& c3,
                                        uint32_t a0, uint32_t a1, uint32_t a2, uint32_t a3,
                                        uint32_t b0, uint32_t b1) {
    asm volatile(
        "mma.sync.aligned.m16n8k16.row.col.f32.f16.f16.f32 "
        "{%0,%1,%2,%3}, {%4,%5,%6,%7}, {%8,%9}, {%0,%1,%2,%3};"
        : "+f"(c0), "+f"(c1), "+f"(c2), "+f"(c3)
        : "r"(a0), "r"(a1), "r"(a2), "r"(a3), "r"(b0), "r"(b1));
}
__device__ __forceinline__ void ldsm4(uint32_t& r0, uint32_t& r1, uint32_t& r2,
                                      uint32_t& r3, uint32_t addr) {
    asm volatile("ldmatrix.sync.aligned.m8n8.x4.shared.b16 {%0,%1,%2,%3}, [%4];"
                 : "=r"(r0), "=r"(r1), "=r"(r2), "=r"(r3) : "r"(addr));
}

// ---------------------------------------------------------------------------
// fused fp32 -> fp16 convert for all 5 tensors (one launch)
// ---------------------------------------------------------------------------
#define W1 (SEQ * EMB / 2)
#define W2 (512 * EMB / 2)
#define WTOT (3 * W1 + 2 * W2)

__global__ __launch_bounds__(256) void cvt_all(
    const float* __restrict__ x,   const float* __restrict__ Wq,
    const float* __restrict__ Wlk, const float* __restrict__ Wlv,
    const float* __restrict__ Wo)
{
    int i = blockIdx.x * 256 + threadIdx.x;
    if (i >= WTOT) return;
    const float* src;
    uint16_t* dst;
    int off;
    if (i < W1)               { src = x;   dst = g_xh;               off = i; }
    else if (i < 2 * W1)      { src = Wq;  dst = g_wh;               off = i - W1; }
    else if (i < 2 * W1 + W2) { src = Wlk; dst = g_wh + 2048 * EMB;  off = i - 2 * W1; }
    else if (i < 2 * W1 + 2 * W2) { src = Wlv; dst = g_wh + 2560 * EMB; off = i - 2 * W1 - W2; }
    else                      { src = Wo;  dst = g_woh;              off = i - 2 * W1 - 2 * W2; }
    float2 v = ((const float2*)src)[off];
    ((uint32_t*)dst)[off] = pack_f16(v.x, v.y);
}

// ---------------------------------------------------------------------------
// fp16 GEMM: C[128x128] = A[128xK] @ B[128xK]^T  (NT, K-major, fp16 in)
// 256 threads = 8 warps (2 x 4), warp tile 64x32, BK=32,
// 3-stage cp.async pipeline, 2 CTAs/SM.
// Prefetch issued AFTER compute (consumer ldsm first — LSU queue order).
// ---------------------------------------------------------------------------
#define BK     32
#define NCH    (EMB / BK)           // 64
#define ROWW   20                   // words per smem row
#define TILEB  (128 * ROWW * 4)     // 10240 bytes (A or B, one stage)
#define STAGEB (2 * TILEB)          // 20480 bytes per stage (A+B)
#define NSTAGE 3
#define GEMM_SMEM (NSTAGE * STAGEB) // 61440 B

template<int OUT16>
__device__ __forceinline__ void gemm_core_h(
    const uint16_t* __restrict__ A, const uint16_t* __restrict__ B,
    void* __restrict__ Cv, int ldc, float escale, char* sm)
{
    const uint32_t sbase = smem_u32(sm);
    const int tid  = threadIdx.x;
    const int wid  = tid >> 5;
    const int lane = tid & 31;
    const int wr   = wid >> 2;
    const int wc   = wid & 3;
    const int g    = lane >> 2;
    const int tig  = lane & 3;
    const int lq   = lane & 7;
    const int lb3  = (lane >> 3) & 1;
    const int lb4  = lane >> 4;

    const uint32_t a_frag = sbase + (uint32_t)((wr * 64 + lq + lb3 * 8) * 80 + lb4 * 16);
    const uint32_t b_frag = sbase + TILEB
                          + (uint32_t)((wc * 32 + lq + lb4 * 8) * 80 + lb3 * 16);

    float acc[4][4][4];
#pragma unroll
    for (int mi = 0; mi < 4; ++mi)
#pragma unroll
        for (int ni = 0; ni < 4; ++ni)
#pragma unroll
            for (int r = 0; r < 4; ++r) acc[mi][ni][r] = 0.f;

    auto loadTiles = [&](int kc) {
        const uint32_t stg = (uint32_t)(kc % NSTAGE) * STAGEB;
        const uint32_t abuf = sbase + stg;
        const uint32_t bbuf = sbase + stg + TILEB;
#pragma unroll
        for (int i = 0; i < 2; ++i) {
            int cid = tid + i * 256;        // 512 chunks: row = cid>>2, c = cid&3
            int row = cid >> 2, c = cid & 3;
            CP_ASYNC16(abuf + row * 80 + c * 16, A + (size_t)row * EMB + kc * BK + c * 8);
            CP_ASYNC16(bbuf + row * 80 + c * 16, B + (size_t)row * EMB + kc * BK + c * 8);
        }
    };

    loadTiles(0); CP_COMMIT();
    loadTiles(1); CP_COMMIT();

    for (int kc = 0; kc < NCH; ++kc) {
        if (kc < NCH - 1) { CP_WAIT(1); }
        else              { CP_WAIT(0); }
        __syncthreads();

        const uint32_t boff = (uint32_t)(kc % NSTAGE) * STAGEB;

#pragma unroll
        for (int s = 0; s < 2; ++s) {
            uint32_t af[4][4], bf[4][2];
#pragma unroll
            for (int mi = 0; mi < 4; ++mi)
                ldsm4(af[mi][0], af[mi][1], af[mi][2], af[mi][3],
                      a_frag + boff + s * 32 + mi * 1280);
            ldsm4(bf[0][0], bf[0][1], bf[1][0], bf[1][1], b_frag + boff + s * 32);
            ldsm4(bf[2][0], bf[2][1], bf[3][0], bf[3][1], b_frag + boff + s * 32 + 1280);
#pragma unroll
            for (int mi = 0; mi < 4; ++mi)
#pragma unroll
                for (int ni = 0; ni < 4; ++ni)
                    mma_f16(acc[mi][ni][0], acc[mi][ni][1], acc[mi][ni][2], acc[mi][ni][3],
                            af[mi][0], af[mi][1], af[mi][2], af[mi][3],
                            bf[ni][0], bf[ni][1]);
        }

        // prefetch AFTER compute: cp.asyncs fill the MMA shadow and never
        // block the next iteration's ldmatrix at the LSU queue.
        if (kc + 2 < NCH) { loadTiles(kc + 2); CP_COMMIT(); }
    }

#pragma unroll
    for (int mi = 0; mi < 4; ++mi) {
        const int r = wr * 64 + mi * 16 + g;
#pragma unroll
        for (int ni = 0; ni < 4; ++ni) {
            const int c = wc * 32 + ni * 8 + tig * 2;
            if (OUT16) {
                uint16_t* C16 = (uint16_t*)Cv;
                *(uint32_t*)(C16 + (size_t)r * ldc + c) =
                    pack_f16(acc[mi][ni][0] * escale, acc[mi][ni][1] * escale);
                *(uint32_t*)(C16 + (size_t)(r + 8) * ldc + c) =
                    pack_f16(acc[mi][ni][2] * escale, acc[mi][ni][3] * escale);
            } else {
                float* C = (float*)Cv;
                *(float2*)(C + (size_t)r * ldc + c) =
                    make_float2(acc[mi][ni][0], acc[mi][ni][1]);
                *(float2*)(C + (size_t)(r + 8) * ldc + c) =
                    make_float2(acc[mi][ni][2], acc[mi][ni][3]);
            }
        }
    }
}

// GEMM1: g_qlkv = xh @ wh^T  (fp16 out; q columns pre-scaled by CEXP)
__global__ __launch_bounds__(256, 2) void gemm1_h()
{
    extern __shared__ __align__(16) char sm[];
    const int n0 = blockIdx.x * 128;
    const int m0 = blockIdx.y * 128;
    const float escale = (n0 < 2048) ? CEXP : 1.0f;
    gemm_core_h<1>(g_xh + (size_t)m0 * EMB, g_wh + (size_t)n0 * EMB,
                   g_qlkv + (size_t)m0 * NQKV + n0, NQKV, escale, sm);
}

// GEMM2: out = aoh @ woh^T  (fp32 out)
__global__ __launch_bounds__(256, 2) void gemm2_h(float* __restrict__ out)
{
    extern __shared__ __align__(16) char sm[];
    const int n0 = blockIdx.x * 128;
    const int m0 = blockIdx.y * 128;
    gemm_core_h<0>(g_aoh + (size_t)m0 * EMB, g_woh + (size_t)n0 * EMB,
                   out + (size_t)m0 * EMB + n0, EMB, 1.0f, sm);
}

// ---------------------------------------------------------------------------
// V transpose: g_qlkv lv section [t][2560 + h*32 + d] -> g_vT[h][d][t]
// ---------------------------------------------------------------------------
__global__ __launch_bounds__(256) void transpose_v()
{
    __shared__ uint16_t tile[32 * 136];
    const int h  = blockIdx.y;
    const int t0 = blockIdx.x * 128;
    const int tid = threadIdx.x;
#pragma unroll
    for (int i = 0; i < 8; ++i) {
        int w = tid + i * 256;              // 2048 words: t = w>>4, dp = w&15
        int t = w >> 4, dp = w & 15;
        uint32_t v = *(const uint32_t*)(g_qlkv + (size_t)(t0 + t) * NQKV + 2560 + h * 32 + dp * 2);
        tile[(2 * dp) * 136 + t]     = (uint16_t)(v & 0xFFFF);
        tile[(2 * dp + 1) * 136 + t] = (uint16_t)(v >> 16);
    }
    __syncthreads();
#pragma unroll
    for (int i = 0; i < 8; ++i) {
        int o = tid + i * 256;              // 2048 words: d = o>>6, tw = o&63
        int d = o >> 6, tw = o & 63;
        uint32_t v = *(const uint32_t*)(tile + d * 136 + tw * 2);
        *(uint32_t*)(g_vT + (size_t)(h * 32 + d) * SEQ + t0 + tw * 2) = v;
    }
}

// ---------------------------------------------------------------------------
// fp16 tensor-core flash attention (max-free softmax), P in registers,
// q pre-scaled by CEXP -> softmax is a bare ex2 on the accumulator.
// 3-stage KV cp.async pipeline, ONE barrier per s-tile; prefetch issued
// AFTER compute (consumer ldsm first at the LSU).
// CTA: one (h, grp), 128 q-rows, 8 warps x 16 rows, 16 s-tiles of 128.
// 2 CTAs/SM (smem 67.1KB, regs capped 128).
// ---------------------------------------------------------------------------
#define KTW    (128 * ROWW)                 // 2560 words per K tile
#define VTW    (32 * 68)                    // 2176 words per V tile
#define KVW    (KTW + VTW)                  // 4736 words per buffer
#define NKVSTG 3
#define QS_OFFW (NKVSTG * KVW)              // Q staging after the KV stages
#define ATTN_SMEM ((QS_OFFW + 128 * ROWW) * 4)    // 67072 bytes

__global__ __launch_bounds__(256, 2) void attn_h()
{
    extern __shared__ __align__(16) char sm[];
    uint32_t* smw = (uint32_t*)sm;
    const uint32_t sbase = smem_u32(sm);
    const int hg  = blockIdx.y;
    const int h   = hg >> 2;
    const int grp = hg & 3;
    const int q0  = blockIdx.x * 128;
    const int tid = threadIdx.x;
    const int wid = tid >> 5;
    const int lane = tid & 31;
    const int g   = lane >> 2;
    const int tig = lane & 3;
    const int lq  = lane & 7;
    const int lb3 = (lane >> 3) & 1;
    const int lb4 = lane >> 4;
    const int qcol = h * 128 + grp * 32;

    // per-lane ldmatrix address components
    const uint32_t k_frag = (uint32_t)((lq + lb4 * 8) * 80 + lb3 * 16);
    const uint32_t v_frag = (uint32_t)(KTW * 4 + (lq + lb4 * 8) * 272 + lb3 * 16);

    // ---- stage Q tile (fp16, pre-scaled by CEXP), 20-word rows
    uint32_t* Qs = smw + QS_OFFW;
#pragma unroll
    for (int i = 0; i < 2; ++i) {
        int cid = tid + i * 256;            // 512 chunks: row = cid>>2, c = cid&3
        int row = cid >> 2, c = cid & 3;
        uint4 v = *(const uint4*)(g_qlkv + (size_t)(q0 + row) * NQKV + qcol + c * 8);
        *(uint4*)(Qs + row * ROWW + c * 4) = v;
    }
    __syncthreads();

    uint32_t qa[2][4];
    {
        const uint32_t q_frag = sbase + QS_OFFW * 4
                              + (uint32_t)((wid * 16 + lq + lb3 * 8) * 80 + lb4 * 16);
#pragma unroll
        for (int s = 0; s < 2; ++s)
            ldsm4(qa[s][0], qa[s][1], qa[s][2], qa[s][3], q_frag + s * 32);
    }

    float o[4][4];
#pragma unroll
    for (int nd = 0; nd < 4; ++nd)
#pragma unroll
        for (int r = 0; r < 4; ++r) o[nd][r] = 0.f;
    float lsum0 = 0.f, lsum1 = 0.f;

    auto prefetch = [&](int st) {
        const uint32_t stg = (uint32_t)(st % NKVSTG) * (KVW * 4);
        uint32_t kb = sbase + stg;
        uint32_t vb = kb + KTW * 4;
        const uint16_t* kp = g_qlkv + (size_t)(st * 128) * NQKV + 2048 + h * 32;
        const uint16_t* vp = g_vT + (size_t)(h * 32) * SEQ + st * 128;
#pragma unroll
        for (int i = 0; i < 2; ++i) {
            int cid = tid + i * 256;
            {   // K: 512 chunks, row = cid>>2 (0..127), c = cid&3
                int row = cid >> 2, c = cid & 3;
                CP_ASYNC16(kb + row * 80 + c * 16, kp + (size_t)row * NQKV + c * 8);
            }
            {   // V: 512 chunks, row d = cid>>4 (0..31), c = cid&15
                int d = cid >> 4, c = cid & 15;
                CP_ASYNC16(vb + d * 272 + c * 16, vp + (size_t)d * SEQ + c * 8);
            }
        }
    };

    prefetch(0); CP_COMMIT();
    prefetch(1); CP_COMMIT();

    for (int st = 0; st < 16; ++st) {
        if (st < 15) { CP_WAIT(1); }
        else         { CP_WAIT(0); }
        __syncthreads();

        const uint32_t stg = (uint32_t)(st % NKVSTG) * (KVW * 4);
        const uint32_t kbase = sbase + stg + k_frag;
        const uint32_t vbase = sbase + stg + v_frag;

        // ---- S = Q @ K^T  (q pre-scaled: acc is already log2-domain score)
        float acc[16][4];
#pragma unroll
        for (int ni = 0; ni < 16; ++ni)
#pragma unroll
            for (int r = 0; r < 4; ++r) acc[ni][r] = 0.f;

#pragma unroll
        for (int p = 0; p < 8; ++p) {
#pragma unroll
            for (int s = 0; s < 2; ++s) {
                uint32_t f0, f1, f2, f3;   // (ni=2p,k0)(2p,k8)(2p+1,k0)(2p+1,k8)
                ldsm4(f0, f1, f2, f3, kbase + p * 1280 + s * 32);
                mma_f16(acc[2*p][0], acc[2*p][1], acc[2*p][2], acc[2*p][3],
                        qa[s][0], qa[s][1], qa[s][2], qa[s][3], f0, f1);
                mma_f16(acc[2*p+1][0], acc[2*p+1][1], acc[2*p+1][2], acc[2*p+1][3],
                        qa[s][0], qa[s][1], qa[s][2], qa[s][3], f2, f3);
            }
        }

        // ---- softmax + P@V fused per k16 chunk; P never leaves registers.
#pragma unroll
        for (int kc = 0; kc < 8; ++kc) {
            const int n0i = 2 * kc, n1i = 2 * kc + 1;
            float a0 = ex2(acc[n0i][0]), a1 = ex2(acc[n0i][1]);
            float a2 = ex2(acc[n0i][2]), a3 = ex2(acc[n0i][3]);
            float b0 = ex2(acc[n1i][0]), b1 = ex2(acc[n1i][1]);
            float b2 = ex2(acc[n1i][2]), b3 = ex2(acc[n1i][3]);
            lsum0 += (a0 + a1) + (b0 + b1);
            lsum1 += (a2 + a3) + (b2 + b3);
            uint32_t pa0 = pack_f16(a0, a1);   // row g,   k 2tig..+1  (tile n0i)
            uint32_t pa1 = pack_f16(a2, a3);   // row g+8, k 2tig..+1
            uint32_t pa2 = pack_f16(b0, b1);   // row g,   k 8+2tig..+1 (tile n1i)
            uint32_t pa3 = pack_f16(b2, b3);   // row g+8, k 8+2tig..+1
            uint32_t vf[4][2];
            ldsm4(vf[0][0], vf[0][1], vf[1][0], vf[1][1], vbase + kc * 32);
            ldsm4(vf[2][0], vf[2][1], vf[3][0], vf[3][1], vbase + 16 * 272 + kc * 32);
#pragma unroll
            for (int nd = 0; nd < 4; ++nd)
                mma_f16(o[nd][0], o[nd][1], o[nd][2], o[nd][3],
                        pa0, pa1, pa2, pa3, vf[nd][0], vf[nd][1]);
        }

        // prefetch AFTER compute: safe (stage (st+2)%3 last read at st-1,
        // and the top-of-st barrier proves all warps are past that), and the
        // cp.asyncs land in the MMA shadow instead of ahead of ldmatrix.
        if (st + 2 < 16) { prefetch(st + 2); CP_COMMIT(); }
    }

    // ---- finalize: quad-reduce row sums, normalize, store fp16
    lsum0 += __shfl_xor_sync(0xFFFFFFFFu, lsum0, 1);
    lsum0 += __shfl_xor_sync(0xFFFFFFFFu, lsum0, 2);
    lsum1 += __shfl_xor_sync(0xFFFFFFFFu, lsum1, 1);
    lsum1 += __shfl_xor_sync(0xFFFFFFFFu, lsum1, 2);
    const float inv0 = 1.f / lsum0;
    const float inv1 = 1.f / lsum1;

    const int qr = q0 + wid * 16 + g;
    uint16_t* op0 = g_aoh + (size_t)qr * EMB + qcol;
    uint16_t* op1 = g_aoh + (size_t)(qr + 8) * EMB + qcol;
#pragma unroll
    for (int nd = 0; nd < 4; ++nd) {
        *(uint32_t*)(op0 + 8 * nd + 2 * tig) = pack_f16(o[nd][0] * inv0, o[nd][1] * inv0);
        *(uint32_t*)(op1 + 8 * nd + 2 * tig) = pack_f16(o[nd][2] * inv1, o[nd][3] * inv1);
    }
}

// ---------------------------------------------------------------------------
extern "C" void kernel_launch(void* const* d_in, const int* in_sizes, int n_in,
                              void* d_out, int out_size)
{
    const float* x   = (const float*)d_in[0];
    const float* Wq  = (const float*)d_in[1];
    // d_in[2] (Wk) and d_in[3] (Wv) are dead in the reference forward — skipped.
    const float* Wlk = (const float*)d_in[4];
    const float* Wlv = (const float*)d_in[5];
    const float* Wo  = (const float*)d_in[6];
    float* out = (float*)d_out;

    cudaFuncSetAttribute(gemm1_h, cudaFuncAttributeMaxDynamicSharedMemorySize, GEMM_SMEM);
    cudaFuncSetAttribute(gemm2_h, cudaFuncAttributeMaxDynamicSharedMemorySize, GEMM_SMEM);
    cudaFuncSetAttribute(attn_h,  cudaFuncAttributeMaxDynamicSharedMemorySize, ATTN_SMEM);

    cvt_all<<<(WTOT + 255) / 256, 256>>>(x, Wq, Wlk, Wlv, Wo);
    gemm1_h<<<dim3(NQKV / 128, SEQ / 128), 256, GEMM_SMEM>>>();
    transpose_v<<<dim3(SEQ / 128, NHEADS), 256>>>();
    attn_h<<<dim3(SEQ / 128, NHEADS * 4), 256, ATTN_SMEM>>>();
    gemm2_h<<<dim3(EMB / 128, SEQ / 128), 256, GEMM_SMEM>>>(out);
}

// round 17
// speedup vs baseline: 1.0957x; 1.0084x over previous
#include <cuda_runtime.h>
#include <cstdint>

#define SEQ    2048
#define EMB    2048
#define NQKV   3072
#define NHEADS 16
#define CEXP   0.12751743200183823f            // (1/sqrt(128)) * log2(e)

// fp16 scratch (allocation-free rule: __device__ globals)
__device__ uint16_t g_xh  [SEQ * EMB];         // x fp16
__device__ uint16_t g_wh  [NQKV * EMB];        // concat(Wq, Wlk, Wlv) fp16
__device__ uint16_t g_woh [EMB * EMB];         // Wo fp16
__device__ uint16_t g_qlkv[SEQ * NQKV];        // q*CEXP | lk | lv  fp16
__device__ uint16_t g_vT  [NHEADS * 32 * SEQ]; // lv transposed: [h][d][t]
__device__ uint16_t g_aoh [SEQ * EMB];         // attention out fp16

// ---------------------------------------------------------------------------
// helpers
// ---------------------------------------------------------------------------
__device__ __forceinline__ uint32_t pack_f16(float lo, float hi) {
    uint32_t r;
    asm("cvt.rn.f16x2.f32 %0, %1, %2;" : "=r"(r) : "f"(hi), "f"(lo));
    return r;
}
__device__ __forceinline__ float ex2(float x) {
    float r;
    asm("ex2.approx.ftz.f32 %0, %1;" : "=f"(r) : "f"(x));
    return r;
}
#define CP_ASYNC16(dst, src) \
    asm volatile("cp.async.cg.shared.global [%0], [%1], 16;" :: "r"(dst), "l"(src))
#define CP_COMMIT() asm volatile("cp.async.commit_group;" ::: "memory")
#define CP_WAIT(n)  asm volatile("cp.async.wait_group %0;" :: "n"(n) : "memory")

__device__ __forceinline__ uint32_t smem_u32(const void* p) {
    uint32_t a;
    asm("{ .reg .u64 t; cvta.to.shared.u64 t, %1; cvt.u32.u64 %0, t; }"
        : "=r"(a) : "l"(p));
    return a;
}
__device__ __forceinline__ void mma_f16(float& c0, float& c1, float& c2, float& c3,
                                        uint32_t a0, uint32_t a1, uint32_t a2, uint32_t a3,
                                        uint32_t b0, uint32_t b1) {
    asm volatile(
        "mma.sync.aligned.m16n8k16.row.col.f32.f16.f16.f32 "
        "{%0,%1,%2,%3}, {%4,%5,%6,%7}, {%8,%9}, {%0,%1,%2,%3};"
        : "+f"(c0), "+f"(c1), "+f"(c2), "+f"(c3)
        : "r"(a0), "r"(a1), "r"(a2), "r"(a3), "r"(b0), "r"(b1));
}
__device__ __forceinline__ void ldsm4(uint32_t& r0, uint32_t& r1, uint32_t& r2,
                                      uint32_t& r3, uint32_t addr) {
    asm volatile("ldmatrix.sync.aligned.m8n8.x4.shared.b16 {%0,%1,%2,%3}, [%4];"
                 : "=r"(r0), "=r"(r1), "=r"(r2), "=r"(r3) : "r"(addr));
}

// ---------------------------------------------------------------------------
// fused fp32 -> fp16 convert for all 5 tensors (one launch)
// ---------------------------------------------------------------------------
#define W1 (SEQ * EMB / 2)
#define W2 (512 * EMB / 2)
#define WTOT (3 * W1 + 2 * W2)

__global__ __launch_bounds__(256) void cvt_all(
    const float* __restrict__ x,   const float* __restrict__ Wq,
    const float* __restrict__ Wlk, const float* __restrict__ Wlv,
    const float* __restrict__ Wo)
{
    int i = blockIdx.x * 256 + threadIdx.x;
    if (i >= WTOT) return;
    const float* src;
    uint16_t* dst;
    int off;
    if (i < W1)               { src = x;   dst = g_xh;               off = i; }
    else if (i < 2 * W1)      { src = Wq;  dst = g_wh;               off = i - W1; }
    else if (i < 2 * W1 + W2) { src = Wlk; dst = g_wh + 2048 * EMB;  off = i - 2 * W1; }
    else if (i < 2 * W1 + 2 * W2) { src = Wlv; dst = g_wh + 2560 * EMB; off = i - 2 * W1 - W2; }
    else                      { src = Wo;  dst = g_woh;              off = i - 2 * W1 - 2 * W2; }
    float2 v = ((const float2*)src)[off];
    ((uint32_t*)dst)[off] = pack_f16(v.x, v.y);
}

// ---------------------------------------------------------------------------
// fp16 GEMM: C[128x128] = A[128xK] @ B[128xK]^T  (NT, K-major, fp16 in)
// 256 threads = 8 warps (2 x 4), warp tile 64x32, BK=32,
// 3-stage cp.async pipeline, 2 CTAs/SM.
// Prefetch issued AFTER compute (consumer ldsm first — LSU queue order).
// ---------------------------------------------------------------------------
#define BK     32
#define NCH    (EMB / BK)           // 64
#define ROWW   20                   // words per smem row
#define TILEB  (128 * ROWW * 4)     // 10240 bytes (A or B, one stage)
#define STAGEB (2 * TILEB)          // 20480 bytes per stage (A+B)
#define NSTAGE 3
#define GEMM_SMEM (NSTAGE * STAGEB) // 61440 B

template<int OUT16>
__device__ __forceinline__ void gemm_core_h(
    const uint16_t* __restrict__ A, const uint16_t* __restrict__ B,
    void* __restrict__ Cv, int ldc, float escale, char* sm)
{
    const uint32_t sbase = smem_u32(sm);
    const int tid  = threadIdx.x;
    const int wid  = tid >> 5;
    const int lane = tid & 31;
    const int wr   = wid >> 2;
    const int wc   = wid & 3;
    const int g    = lane >> 2;
    const int tig  = lane & 3;
    const int lq   = lane & 7;
    const int lb3  = (lane >> 3) & 1;
    const int lb4  = lane >> 4;

    const uint32_t a_frag = sbase + (uint32_t)((wr * 64 + lq + lb3 * 8) * 80 + lb4 * 16);
    const uint32_t b_frag = sbase + TILEB
                          + (uint32_t)((wc * 32 + lq + lb4 * 8) * 80 + lb3 * 16);

    float acc[4][4][4];
#pragma unroll
    for (int mi = 0; mi < 4; ++mi)
#pragma unroll
        for (int ni = 0; ni < 4; ++ni)
#pragma unroll
            for (int r = 0; r < 4; ++r) acc[mi][ni][r] = 0.f;

    auto loadTiles = [&](int kc) {
        const uint32_t stg = (uint32_t)(kc % NSTAGE) * STAGEB;
        const uint32_t abuf = sbase + stg;
        const uint32_t bbuf = sbase + stg + TILEB;
#pragma unroll
        for (int i = 0; i < 2; ++i) {
            int cid = tid + i * 256;        // 512 chunks: row = cid>>2, c = cid&3
            int row = cid >> 2, c = cid & 3;
            CP_ASYNC16(abuf + row * 80 + c * 16, A + (size_t)row * EMB + kc * BK + c * 8);
            CP_ASYNC16(bbuf + row * 80 + c * 16, B + (size_t)row * EMB + kc * BK + c * 8);
        }
    };

    loadTiles(0); CP_COMMIT();
    loadTiles(1); CP_COMMIT();

    for (int kc = 0; kc < NCH; ++kc) {
        if (kc < NCH - 1) { CP_WAIT(1); }
        else              { CP_WAIT(0); }
        __syncthreads();

        const uint32_t boff = (uint32_t)(kc % NSTAGE) * STAGEB;

#pragma unroll
        for (int s = 0; s < 2; ++s) {
            uint32_t af[4][4], bf[4][2];
#pragma unroll
            for (int mi = 0; mi < 4; ++mi)
                ldsm4(af[mi][0], af[mi][1], af[mi][2], af[mi][3],
                      a_frag + boff + s * 32 + mi * 1280);
            ldsm4(bf[0][0], bf[0][1], bf[1][0], bf[1][1], b_frag + boff + s * 32);
            ldsm4(bf[2][0], bf[2][1], bf[3][0], bf[3][1], b_frag + boff + s * 32 + 1280);
#pragma unroll
            for (int mi = 0; mi < 4; ++mi)
#pragma unroll
                for (int ni = 0; ni < 4; ++ni)
                    mma_f16(acc[mi][ni][0], acc[mi][ni][1], acc[mi][ni][2], acc[mi][ni][3],
                            af[mi][0], af[mi][1], af[mi][2], af[mi][3],
                            bf[ni][0], bf[ni][1]);
        }

        // prefetch AFTER compute: cp.asyncs fill the MMA shadow and never
        // block the next iteration's ldmatrix at the LSU queue.
        if (kc + 2 < NCH) { loadTiles(kc + 2); CP_COMMIT(); }
    }

#pragma unroll
    for (int mi = 0; mi < 4; ++mi) {
        const int r = wr * 64 + mi * 16 + g;
#pragma unroll
        for (int ni = 0; ni < 4; ++ni) {
            const int c = wc * 32 + ni * 8 + tig * 2;
            if (OUT16) {
                uint16_t* C16 = (uint16_t*)Cv;
                *(uint32_t*)(C16 + (size_t)r * ldc + c) =
                    pack_f16(acc[mi][ni][0] * escale, acc[mi][ni][1] * escale);
                *(uint32_t*)(C16 + (size_t)(r + 8) * ldc + c) =
                    pack_f16(acc[mi][ni][2] * escale, acc[mi][ni][3] * escale);
            } else {
                float* C = (float*)Cv;
                *(float2*)(C + (size_t)r * ldc + c) =
                    make_float2(acc[mi][ni][0], acc[mi][ni][1]);
                *(float2*)(C + (size_t)(r + 8) * ldc + c) =
                    make_float2(acc[mi][ni][2], acc[mi][ni][3]);
            }
        }
    }
}

// GEMM1: g_qlkv = xh @ wh^T  (fp16 out; q columns pre-scaled by CEXP)
__global__ __launch_bounds__(256, 2) void gemm1_h()
{
    extern __shared__ __align__(16) char sm[];
    const int n0 = blockIdx.x * 128;
    const int m0 = blockIdx.y * 128;
    const float escale = (n0 < 2048) ? CEXP : 1.0f;
    gemm_core_h<1>(g_xh + (size_t)m0 * EMB, g_wh + (size_t)n0 * EMB,
                   g_qlkv + (size_t)m0 * NQKV + n0, NQKV, escale, sm);
}

// GEMM2: out = aoh @ woh^T  (fp32 out)
__global__ __launch_bounds__(256, 2) void gemm2_h(float* __restrict__ out)
{
    extern __shared__ __align__(16) char sm[];
    const int n0 = blockIdx.x * 128;
    const int m0 = blockIdx.y * 128;
    gemm_core_h<0>(g_aoh + (size_t)m0 * EMB, g_woh + (size_t)n0 * EMB,
                   out + (size_t)m0 * EMB + n0, EMB, 1.0f, sm);
}

// ---------------------------------------------------------------------------
// V transpose: g_qlkv lv section [t][2560 + h*32 + d] -> g_vT[h][d][t]
// ---------------------------------------------------------------------------
__global__ __launch_bounds__(256) void transpose_v()
{
    __shared__ uint16_t tile[32 * 136];
    const int h  = blockIdx.y;
    const int t0 = blockIdx.x * 128;
    const int tid = threadIdx.x;
#pragma unroll
    for (int i = 0; i < 8; ++i) {
        int w = tid + i * 256;              // 2048 words: t = w>>4, dp = w&15
        int t = w >> 4, dp = w & 15;
        uint32_t v = *(const uint32_t*)(g_qlkv + (size_t)(t0 + t) * NQKV + 2560 + h * 32 + dp * 2);
        tile[(2 * dp) * 136 + t]     = (uint16_t)(v & 0xFFFF);
        tile[(2 * dp + 1) * 136 + t] = (uint16_t)(v >> 16);
    }
    __syncthreads();
#pragma unroll
    for (int i = 0; i < 8; ++i) {
        int o = tid + i * 256;              // 2048 words: d = o>>6, tw = o&63
        int d = o >> 6, tw = o & 63;
        uint32_t v = *(const uint32_t*)(tile + d * 136 + tw * 2);
        *(uint32_t*)(g_vT + (size_t)(h * 32 + d) * SEQ + t0 + tw * 2) = v;
    }
}

// ---------------------------------------------------------------------------
// fp16 tensor-core flash attention (max-free softmax), P in registers,
// q pre-scaled by CEXP. S computed in two 64-column halves per s-tile:
// halves the transient acc (64 -> 32 regs) with the SAME per-element MMA /
// ex2 / lsum / o sequences (bit-identical) -> fits 3 CTAs/SM.
// 3-stage KV cp.async pipeline, ONE barrier per s-tile; prefetch after
// compute. CTA: one (h, grp), 128 q-rows, 8 warps x 16 rows, 16 s-tiles.
// 3 CTAs/SM (smem 67.1KB x3 = 201KB, regs capped ~85).
// ---------------------------------------------------------------------------
#define KTW    (128 * ROWW)                 // 2560 words per K tile
#define VTW    (32 * 68)                    // 2176 words per V tile
#define KVW    (KTW + VTW)                  // 4736 words per buffer
#define NKVSTG 3
#define QS_OFFW (NKVSTG * KVW)              // Q staging after the KV stages
#define ATTN_SMEM ((QS_OFFW + 128 * ROWW) * 4)    // 67072 bytes

__global__ __launch_bounds__(256, 3) void attn_h()
{
    extern __shared__ __align__(16) char sm[];
    uint32_t* smw = (uint32_t*)sm;
    const uint32_t sbase = smem_u32(sm);
    const int hg  = blockIdx.y;
    const int h   = hg >> 2;
    const int grp = hg & 3;
    const int q0  = blockIdx.x * 128;
    const int tid = threadIdx.x;
    const int wid = tid >> 5;
    const int lane = tid & 31;
    const int g   = lane >> 2;
    const int tig = lane & 3;
    const int lq  = lane & 7;
    const int lb3 = (lane >> 3) & 1;
    const int lb4 = lane >> 4;
    const int qcol = h * 128 + grp * 32;

    // per-lane ldmatrix address components
    const uint32_t k_frag = (uint32_t)((lq + lb4 * 8) * 80 + lb3 * 16);
    const uint32_t v_frag = (uint32_t)(KTW * 4 + (lq + lb4 * 8) * 272 + lb3 * 16);

    // ---- stage Q tile (fp16, pre-scaled by CEXP), 20-word rows
    uint32_t* Qs = smw + QS_OFFW;
#pragma unroll
    for (int i = 0; i < 2; ++i) {
        int cid = tid + i * 256;            // 512 chunks: row = cid>>2, c = cid&3
        int row = cid >> 2, c = cid & 3;
        uint4 v = *(const uint4*)(g_qlkv + (size_t)(q0 + row) * NQKV + qcol + c * 8);
        *(uint4*)(Qs + row * ROWW + c * 4) = v;
    }
    __syncthreads();

    uint32_t qa[2][4];
    {
        const uint32_t q_frag = sbase + QS_OFFW * 4
                              + (uint32_t)((wid * 16 + lq + lb3 * 8) * 80 + lb4 * 16);
#pragma unroll
        for (int s = 0; s < 2; ++s)
            ldsm4(qa[s][0], qa[s][1], qa[s][2], qa[s][3], q_frag + s * 32);
    }

    float o[4][4];
#pragma unroll
    for (int nd = 0; nd < 4; ++nd)
#pragma unroll
        for (int r = 0; r < 4; ++r) o[nd][r] = 0.f;
    float lsum0 = 0.f, lsum1 = 0.f;

    auto prefetch = [&](int st) {
        const uint32_t stg = (uint32_t)(st % NKVSTG) * (KVW * 4);
        uint32_t kb = sbase + stg;
        uint32_t vb = kb + KTW * 4;
        const uint16_t* kp = g_qlkv + (size_t)(st * 128) * NQKV + 2048 + h * 32;
        const uint16_t* vp = g_vT + (size_t)(h * 32) * SEQ + st * 128;
#pragma unroll
        for (int i = 0; i < 2; ++i) {
            int cid = tid + i * 256;
            {   // K: 512 chunks, row = cid>>2 (0..127), c = cid&3
                int row = cid >> 2, c = cid & 3;
                CP_ASYNC16(kb + row * 80 + c * 16, kp + (size_t)row * NQKV + c * 8);
            }
            {   // V: 512 chunks, row d = cid>>4 (0..31), c = cid&15
                int d = cid >> 4, c = cid & 15;
                CP_ASYNC16(vb + d * 272 + c * 16, vp + (size_t)d * SEQ + c * 8);
            }
        }
    };

    prefetch(0); CP_COMMIT();
    prefetch(1); CP_COMMIT();

    for (int st = 0; st < 16; ++st) {
        if (st < 15) { CP_WAIT(1); }
        else         { CP_WAIT(0); }
        __syncthreads();

        const uint32_t stg = (uint32_t)(st % NKVSTG) * (KVW * 4);
        const uint32_t kbase = sbase + stg + k_frag;
        const uint32_t vbase = sbase + stg + v_frag;

        // ---- process the 128 s-columns as two independent 64-column halves
#pragma unroll
        for (int half = 0; half < 2; ++half) {
            // S = Q @ K^T for this half (8 n8-tiles)
            float acc[8][4];
#pragma unroll
            for (int ni = 0; ni < 8; ++ni)
#pragma unroll
                for (int r = 0; r < 4; ++r) acc[ni][r] = 0.f;

#pragma unroll
            for (int p = 0; p < 4; ++p) {
                const int gp = half * 4 + p;
#pragma unroll
                for (int s = 0; s < 2; ++s) {
                    uint32_t f0, f1, f2, f3;
                    ldsm4(f0, f1, f2, f3, kbase + gp * 1280 + s * 32);
                    mma_f16(acc[2*p][0], acc[2*p][1], acc[2*p][2], acc[2*p][3],
                            qa[s][0], qa[s][1], qa[s][2], qa[s][3], f0, f1);
                    mma_f16(acc[2*p+1][0], acc[2*p+1][1], acc[2*p+1][2], acc[2*p+1][3],
                            qa[s][0], qa[s][1], qa[s][2], qa[s][3], f2, f3);
                }
            }

            // softmax + P@V for this half (4 k16 chunks); P in registers
#pragma unroll
            for (int kc = 0; kc < 4; ++kc) {
                const int gc = half * 4 + kc;
                const int n0i = 2 * kc, n1i = 2 * kc + 1;
                float a0 = ex2(acc[n0i][0]), a1 = ex2(acc[n0i][1]);
                float a2 = ex2(acc[n0i][2]), a3 = ex2(acc[n0i][3]);
                float b0 = ex2(acc[n1i][0]), b1 = ex2(acc[n1i][1]);
                float b2 = ex2(acc[n1i][2]), b3 = ex2(acc[n1i][3]);
                lsum0 += (a0 + a1) + (b0 + b1);
                lsum1 += (a2 + a3) + (b2 + b3);
                uint32_t pa0 = pack_f16(a0, a1);
                uint32_t pa1 = pack_f16(a2, a3);
                uint32_t pa2 = pack_f16(b0, b1);
                uint32_t pa3 = pack_f16(b2, b3);
                uint32_t vf[4][2];
                ldsm4(vf[0][0], vf[0][1], vf[1][0], vf[1][1], vbase + gc * 32);
                ldsm4(vf[2][0], vf[2][1], vf[3][0], vf[3][1], vbase + 16 * 272 + gc * 32);
#pragma unroll
                for (int nd = 0; nd < 4; ++nd)
                    mma_f16(o[nd][0], o[nd][1], o[nd][2], o[nd][3],
                            pa0, pa1, pa2, pa3, vf[nd][0], vf[nd][1]);
            }
        }

        // prefetch AFTER compute (stage (st+2)%3 last read at st-1; safe)
        if (st + 2 < 16) { prefetch(st + 2); CP_COMMIT(); }
    }

    // ---- finalize: quad-reduce row sums, normalize, store fp16
    lsum0 += __shfl_xor_sync(0xFFFFFFFFu, lsum0, 1);
    lsum0 += __shfl_xor_sync(0xFFFFFFFFu, lsum0, 2);
    lsum1 += __shfl_xor_sync(0xFFFFFFFFu, lsum1, 1);
    lsum1 += __shfl_xor_sync(0xFFFFFFFFu, lsum1, 2);
    const float inv0 = 1.f / lsum0;
    const float inv1 = 1.f / lsum1;

    const int qr = q0 + wid * 16 + g;
    uint16_t* op0 = g_aoh + (size_t)qr * EMB + qcol;
    uint16_t* op1 = g_aoh + (size_t)(qr + 8) * EMB + qcol;
#pragma unroll
    for (int nd = 0; nd < 4; ++nd) {
        *(uint32_t*)(op0 + 8 * nd + 2 * tig) = pack_f16(o[nd][0] * inv0, o[nd][1] * inv0);
        *(uint32_t*)(op1 + 8 * nd + 2 * tig) = pack_f16(o[nd][2] * inv1, o[nd][3] * inv1);
    }
}

// ---------------------------------------------------------------------------
extern "C" void kernel_launch(void* const* d_in, const int* in_sizes, int n_in,
                              void* d_out, int out_size)
{
    const float* x   = (const float*)d_in[0];
    const float* Wq  = (const float*)d_in[1];
    // d_in[2] (Wk) and d_in[3] (Wv) are dead in the reference forward — skipped.
    const float* Wlk = (const float*)d_in[4];
    const float* Wlv = (const float*)d_in[5];
    const float* Wo  = (const float*)d_in[6];
    float* out = (float*)d_out;

    cudaFuncSetAttribute(gemm1_h, cudaFuncAttributeMaxDynamicSharedMemorySize, GEMM_SMEM);
    cudaFuncSetAttribute(gemm2_h, cudaFuncAttributeMaxDynamicSharedMemorySize, GEMM_SMEM);
    cudaFuncSetAttribute(attn_h,  cudaFuncAttributeMaxDynamicSharedMemorySize, ATTN_SMEM);

    cvt_all<<<(WTOT + 255) / 256, 256>>>(x, Wq, Wlk, Wlv, Wo);
    gemm1_h<<<dim3(NQKV / 128, SEQ / 128), 256, GEMM_SMEM>>>();
    transpose_v<<<dim3(SEQ / 128, NHEADS), 256>>>();
    attn_h<<<dim3(SEQ / 128, NHEADS * 4), 256, ATTN_SMEM>>>();
    gemm2_h<<<dim3(EMB / 128, SEQ / 128), 256, GEMM_SMEM>>>(out);
}